// round 16
// baseline (speedup 1.0000x reference)
#include <cuda_runtime.h>
#include <cuda_fp16.h>
#include <math.h>
#include <cstdint>

// Problem constants
#define NQ   100
#define NT   197
#define BSZ  128
#define E    768
#define NH   12
#define HD   64
#define BH   (BSZ*NH)

// ---------------------------------------------------------------------------
// Device scratch
// ---------------------------------------------------------------------------
__device__ __half g_qh[NQ * BSZ * E];      // fp16 inputs to projections
__device__ __half g_kh[NT * BSZ * E];
__device__ __half g_vh[NT * BSZ * E];
__device__ __half g_wh[3 * E * E];
__device__ __half g_owh[E * E];
__device__ __half g_qph[BH * NQ * HD];     // fp16 projections, [bh][tok][d]
__device__ __half g_kph[BH * NT * HD];
__device__ __half g_vph[BH * NT * HD];
__device__ __half g_yh[NQ * BSZ * E];      // fp16 attention output (row-major)
__device__ __half g_qmH[256 * 112];        // normalized q_mapper fp16 [t][q], zero-pad
__device__ __half g_xmH[128 * 256];        // normalized x_mapper fp16 [q][t], zero-pad

// ---------------------------------------------------------------------------
// Common PTX helpers
// ---------------------------------------------------------------------------
__device__ __forceinline__ uint32_t smem_u32(const void* p) {
    uint32_t a;
    asm("{ .reg .u64 t; cvta.to.shared.u64 t, %1; cvt.u32.u64 %0, t; }"
        : "=r"(a) : "l"(p));
    return a;
}
__device__ __forceinline__ void cpa16(uint32_t dst, const void* src) {
    asm volatile("cp.async.cg.shared.global [%0], [%1], 16;" :: "r"(dst), "l"(src));
}
__device__ __forceinline__ void ldsm4(uint32_t& r0, uint32_t& r1, uint32_t& r2,
                                      uint32_t& r3, uint32_t addr) {
    asm volatile("ldmatrix.sync.aligned.m8n8.x4.shared.b16 {%0,%1,%2,%3}, [%4];"
                 : "=r"(r0), "=r"(r1), "=r"(r2), "=r"(r3) : "r"(addr));
}
__device__ __forceinline__ void ldsm4t(uint32_t& r0, uint32_t& r1, uint32_t& r2,
                                       uint32_t& r3, uint32_t addr) {
    asm volatile("ldmatrix.sync.aligned.m8n8.x4.trans.shared.b16 {%0,%1,%2,%3}, [%4];"
                 : "=r"(r0), "=r"(r1), "=r"(r2), "=r"(r3) : "r"(addr));
}
__device__ __forceinline__ void mma_f16(float* c, const uint32_t* a, const uint32_t* b) {
    asm volatile(
        "mma.sync.aligned.m16n8k16.row.col.f32.f16.f16.f32 "
        "{%0,%1,%2,%3}, {%4,%5,%6,%7}, {%8,%9}, {%0,%1,%2,%3};"
        : "+f"(c[0]), "+f"(c[1]), "+f"(c[2]), "+f"(c[3])
        : "r"(a[0]), "r"(a[1]), "r"(a[2]), "r"(a[3]), "r"(b[0]), "r"(b[1]));
}

// ---------------------------------------------------------------------------
// One fused fp32 -> fp16 conversion for all five tensors
// ---------------------------------------------------------------------------
#define NQ4 (NQ * BSZ * E / 4)
#define NT4 (NT * BSZ * E / 4)
#define W4  (3 * E * E / 4)
#define OW4 (E * E / 4)
#define TOT4 (NQ4 + 2 * NT4 + W4 + OW4)

__global__ void f2h_all(const float4* __restrict__ q, const float4* __restrict__ k,
                        const float4* __restrict__ v, const float4* __restrict__ w,
                        const float4* __restrict__ ow,
                        __half2* qh, __half2* kh, __half2* vh, __half2* wh, __half2* owh)
{
    int i = blockIdx.x * blockDim.x + threadIdx.x;
    if (i >= TOT4) return;
    const float4* src; __half2* dst; int j;
    if (i < NQ4)                        { src = q;  dst = qh;  j = i; }
    else if (i < NQ4 + NT4)             { src = k;  dst = kh;  j = i - NQ4; }
    else if (i < NQ4 + 2 * NT4)         { src = v;  dst = vh;  j = i - NQ4 - NT4; }
    else if (i < NQ4 + 2 * NT4 + W4)    { src = w;  dst = wh;  j = i - NQ4 - 2 * NT4; }
    else                                { src = ow; dst = owh; j = i - NQ4 - 2 * NT4 - W4; }
    float4 val = src[j];
    dst[2 * j]     = __floats2half2_rn(val.x, val.y);
    dst[2 * j + 1] = __floats2half2_rn(val.z, val.w);
}

// ---------------------------------------------------------------------------
// fp16 mma.sync GEMM (unchanged mainloop; scatter epilogue for OUTH=true)
// ---------------------------------------------------------------------------
#define PADH      40
#define MAT_H     (128 * PADH)
#define STG_B     (2 * MAT_H * 2)
#define GEMM_SMEM (4 * STG_B)

template<bool OUTH>
__global__ __launch_bounds__(256, 2)
void gemm_h(const __half* __restrict__ A, const __half* __restrict__ W,
            const float* __restrict__ bias, void* __restrict__ Cv, int NTOK)
{
    extern __shared__ __half smh[];
    const uint32_t sb = smem_u32(smh);
    const int tid  = threadIdx.x;
    const int lane = tid & 31;
    const int wid  = tid >> 5;
    const int m0 = blockIdx.y * 128, n0 = blockIdx.x * 128;
    const int wm = (wid >> 2) * 64;
    const int wn = (wid & 3) * 32;

    const int prow = tid >> 1;
    const int pseg = (tid & 1) * 16;
    const __half* gA = A + (size_t)(m0 + prow) * E + pseg;
    const __half* gB = W + (size_t)(n0 + prow) * E + pseg;
    const uint32_t sAa = sb + (prow * PADH + pseg) * 2;
    const uint32_t sBa = sAa + MAT_H * 2;

#define LOAD_STAGE(st, kc) do { \
    const uint32_t so = (uint32_t)(st) * STG_B; \
    const __half* ga = gA + (kc) * 32; \
    const __half* gb = gB + (kc) * 32; \
    cpa16(sAa + so,      ga);     cpa16(sAa + so + 16, ga + 8); \
    cpa16(sBa + so,      gb);     cpa16(sBa + so + 16, gb + 8); \
    asm volatile("cp.async.commit_group;"); \
} while (0)

    LOAD_STAGE(0, 0);
    LOAD_STAGE(1, 1);
    LOAD_STAGE(2, 2);

    float acc[4][4][4];
#pragma unroll
    for (int i = 0; i < 4; i++)
#pragma unroll
        for (int j = 0; j < 4; j++)
#pragma unroll
            for (int k = 0; k < 4; k++) acc[i][j][k] = 0.0f;

    const int g = lane >> 3, j = lane & 7;
    const uint32_t aoff = ((wm + j + (g & 1) * 8) * PADH + (g >> 1) * 8) * 2;
    const uint32_t boff = ((wn + j + (g & 1) * 8) * PADH + (g >> 1) * 8) * 2 + MAT_H * 2;

    for (int kc = 0; kc < 24; kc++) {
        asm volatile("cp.async.wait_group 2;");
        __syncthreads();
        const uint32_t base = sb + (uint32_t)(kc & 3) * STG_B;

#pragma unroll
        for (int s = 0; s < 2; s++) {
            const uint32_t k0b = s * 32;
            uint32_t bf[4][2];
            ldsm4(bf[0][0], bf[1][0], bf[0][1], bf[1][1], base + boff + k0b);
            ldsm4(bf[2][0], bf[3][0], bf[2][1], bf[3][1],
                  base + boff + 16 * PADH * 2 + k0b);
#pragma unroll
            for (int mt = 0; mt < 4; mt++) {
                uint32_t af[4];
                ldsm4(af[0], af[1], af[2], af[3],
                      base + aoff + mt * 16 * PADH * 2 + k0b);
#pragma unroll
                for (int nt = 0; nt < 4; nt++)
                    mma_f16(acc[mt][nt], af, bf[nt]);
            }
        }
        if (kc + 3 < 24) {
            LOAD_STAGE((kc + 3) & 3, kc + 3);
        } else {
            asm volatile("cp.async.commit_group;");
        }
    }

    const int r = lane >> 2, q = lane & 3;
#pragma unroll
    for (int mt = 0; mt < 4; mt++) {
        const int row = m0 + wm + mt * 16 + r;
#pragma unroll
        for (int nt = 0; nt < 4; nt++) {
            const int col = n0 + wn + nt * 8 + 2 * q;
            const float b0 = bias[col], b1 = bias[col + 1];
            if (OUTH) {
                __half* C = (__half*)Cv;
                const int tok = blockIdx.y;
                const int bb  = row & 127;
                const int h   = col >> 6, d = col & 63;
                const size_t base0 = ((size_t)(bb * NH + h) * NTOK + tok) * HD + d;
                const size_t base1 = ((size_t)(((row + 8) & 127) * NH + h) * NTOK + tok) * HD + d;
                *(__half2*)&C[base0] =
                    __floats2half2_rn(acc[mt][nt][0] + b0, acc[mt][nt][1] + b1);
                *(__half2*)&C[base1] =
                    __floats2half2_rn(acc[mt][nt][2] + b0, acc[mt][nt][3] + b1);
            } else {
                float* C = (float*)Cv;
                *(float2*)&C[(size_t)row * E + col] =
                    make_float2(acc[mt][nt][0] + b0, acc[mt][nt][1] + b1);
                *(float2*)&C[(size_t)(row + 8) * E + col] =
                    make_float2(acc[mt][nt][2] + b0, acc[mt][nt][3] + b1);
            }
        }
    }
#undef LOAD_STAGE
}

// ---------------------------------------------------------------------------
// Normalize mapper matrices -> zero-padded fp16
// ---------------------------------------------------------------------------
__global__ void norm_map_h(const float* __restrict__ qm, const float* __restrict__ xm,
                           __half* __restrict__ qmH, __half* __restrict__ xmH)
{
    int row  = blockIdx.x * (blockDim.x >> 5) + (threadIdx.x >> 5);
    int lane = threadIdx.x & 31;
    const __half hz = __float2half(0.0f);
    if (row < 256) {
        __half* dst = qmH + row * 112;
        if (row < NT) {
            const float* x = qm + row * NQ;
            float ss = 0.0f;
            for (int i = lane; i < NQ; i += 32) { float v = x[i]; ss += v * v; }
#pragma unroll
            for (int o = 16; o; o >>= 1) ss += __shfl_xor_sync(0xffffffffu, ss, o);
            float s = 1.0f / fmaxf(sqrtf(ss), 1e-12f);
            for (int i = lane; i < 112; i += 32)
                dst[i] = (i < NQ) ? __float2half(x[i] * s) : hz;
        } else {
            for (int i = lane; i < 112; i += 32) dst[i] = hz;
        }
    } else if (row < 384) {
        int r = row - 256;
        __half* dst = xmH + r * 256;
        if (r < NQ) {
            const float* x = xm + r * NT;
            float ss = 0.0f;
            for (int i = lane; i < NT; i += 32) { float v = x[i]; ss += v * v; }
#pragma unroll
            for (int o = 16; o; o >>= 1) ss += __shfl_xor_sync(0xffffffffu, ss, o);
            float s = 1.0f / fmaxf(sqrtf(ss), 1e-12f);
            for (int i = lane; i < 256; i += 32)
                dst[i] = (i < NT) ? __float2half(x[i] * s) : hz;
        } else {
            for (int i = lane; i < 256; i += 32) dst[i] = hz;
        }
    }
}

// ---------------------------------------------------------------------------
// Tensor-core fused attention v2.
//  - q/k loaded NATURAL [tok][64] via cp.async (coalesced, no transpose stores)
//  - trans-ldmatrix supplies qn/kn fragments
//  - L2-norm scales rs[128] folded into P2 epilogue (linearity)
//  - parallel register-only softmax (8 threads/row)
// SMEM (halves): sQ[112][72] (later sS/hP) | sK[256][72] (later sOut) |
//                hM[64][264] | rs[128]f
// ---------------------------------------------------------------------------
#define SQ_S 72
#define SK_S 72
#define HM_S 264
#define SS_S 68
#define HP_S 136
#define SO_S 66
#define OFF_SK 8704
#define OFF_HM (OFF_SK + 18432)           // 27136
#define OFF_RS (OFF_HM + 16896)           // 44032 halves
#define ATTN_SMEM_BYTES ((OFF_RS + 256) * 2)   // 88576

__global__ __launch_bounds__(512, 2)
void attn_tc(const __half* __restrict__ q_t, const __half* __restrict__ k_t,
             const __half* __restrict__ v_t, const __half* __restrict__ qmH,
             const __half* __restrict__ xmH, const float* __restrict__ temp,
             __half* __restrict__ y)
{
    extern __shared__ __half sh[];
    __half* sQ = sh;                       // [112][72] natural [tok][d]
    __half* sK = sh + OFF_SK;              // [256][72] natural [tok][e]
    __half* hM = sh + OFF_HM;              // [64][264] k-major qm / x
    float*  sS   = (float*)sh;             // [64][68]  overlays sQ after P1
    float*  sOut = (float*)(sh + OFF_SK);  // [128][66] overlays sK after P2
    float*  rs   = (float*)(sh + OFF_RS);  // [128] 1/norm scales (q:0-63, k:64-127)
    const uint32_t sbase = smem_u32(sh);

    const int bh = blockIdx.x;
    const int b  = bh / NH;
    const int h  = bh % NH;
    const __half* qp = q_t + (size_t)bh * (NQ * HD);
    const __half* kp = k_t + (size_t)bh * (NT * HD);
    const __half* vp = v_t + (size_t)bh * (NT * HD);

    const int tid  = threadIdx.x;
    const int wid  = tid >> 5;
    const int lane = tid & 31;
    const int g    = lane >> 3;
    const int jj   = lane & 7;
    const int r    = lane >> 2;
    const int qq   = lane & 3;

    // ---- zero pad tails: sQ rows 100..111, sK rows 197..255 ----
    {
        uint32_t* zq = (uint32_t*)(sQ + 100 * SQ_S);   // 432 words
        uint32_t* zk = (uint32_t*)(sK + 197 * SK_S);   // 2124 words
        for (int i = tid; i < 432 + 2124; i += 512) {
            if (i < 432) zq[i] = 0u; else zk[i - 432] = 0u;
        }
    }

    // ---- cp.async natural q/k rows (16B segments) ----
    for (int i = tid; i < (NQ + NT) * 8; i += 512) {
        if (i < NQ * 8) {
            int rr = i >> 3, s = i & 7;
            cpa16(sbase + (rr * SQ_S + s * 8) * 2, qp + rr * HD + s * 8);
        } else {
            int k = i - NQ * 8;
            int rr = k >> 3, s = k & 7;
            cpa16(sbase + OFF_SK * 2 + (rr * SK_S + s * 8) * 2, kp + rr * HD + s * 8);
        }
    }
    asm volatile("cp.async.commit_group;");
    asm volatile("cp.async.wait_group 0;");
    __syncthreads();

    // ---- column L2 norms -> rs[128] (warp w handles 8 channels) ----
    {
#pragma unroll
        for (int cc = 0; cc < 8; cc++) {
            int ch = wid * 8 + cc;
            float ss = 0.0f;
            if (ch < 64) {
                for (int i = lane; i < 112; i += 32) {
                    float v = __half2float(sQ[i * SQ_S + ch]); ss += v * v;
                }
            } else {
                int e = ch - 64;
                for (int i = lane; i < 256; i += 32) {
                    float v = __half2float(sK[i * SK_S + e]); ss += v * v;
                }
            }
#pragma unroll
            for (int o = 16; o; o >>= 1) ss += __shfl_xor_sync(0xffffffffu, ss, o);
            if (lane == 0) rs[ch] = 1.0f / fmaxf(sqrtf(ss), 1e-12f);
        }
    }
    __syncthreads();

    // ---- P1: qm[64,256] = q @ qmH^T -> hM (A via trans-ldsm from natural sQ) ----
    {
        const int mb = (wid & 3) * 16;
        const int nb = (wid >> 2) * 64;
        const uint32_t aBase = sbase +
            ((jj + (g >> 1) * 8) * SQ_S + mb + (g & 1) * 8) * 2;
        float acc[8][4];
#pragma unroll
        for (int i = 0; i < 8; i++)
#pragma unroll
            for (int k = 0; k < 4; k++) acc[i][k] = 0.0f;
        const int k0l = 2 * qq;
#pragma unroll
        for (int kk = 0; kk < 7; kk++) {
            uint32_t af[4];
            ldsm4t(af[0], af[1], af[2], af[3], aBase + kk * 16 * SQ_S * 2);
#pragma unroll
            for (int nb8 = 0; nb8 < 8; nb8++) {
                const __half* bp = qmH + (nb + nb8 * 8 + r) * 112 + kk * 16 + k0l;
                uint32_t bf[2];
                bf[0] = *(const uint32_t*)bp;
                bf[1] = *(const uint32_t*)(bp + 8);
                mma_f16(acc[nb8], af, bf);
            }
        }
#pragma unroll
        for (int nb8 = 0; nb8 < 8; nb8++) {
            int col = nb + nb8 * 8 + 2 * qq;
            *(__half2*)&hM[(mb + r) * HM_S + col]     = __floats2half2_rn(acc[nb8][0], acc[nb8][1]);
            *(__half2*)&hM[(mb + r + 8) * HM_S + col] = __floats2half2_rn(acc[nb8][2], acc[nb8][3]);
        }
    }
    __syncthreads();

    // ---- P2: S[64,64] = qm @ k^T -> sS fp32, scaled by temp*rs_q*rs_k ----
    {
        const int mb = (wid & 3) * 16;
        const int nb = (wid >> 2) * 16;
        const uint32_t aBase = sbase +
            (OFF_HM + (mb + jj + (g & 1) * 8) * HM_S + (g >> 1) * 8) * 2;
        const uint32_t bBase = sbase +
            (OFF_SK + (jj + (g >> 1) * 8) * SK_S + nb + (g & 1) * 8) * 2;
        float acc[2][4];
#pragma unroll
        for (int i = 0; i < 2; i++)
#pragma unroll
            for (int k = 0; k < 4; k++) acc[i][k] = 0.0f;
#pragma unroll
        for (int kk = 0; kk < 16; kk++) {
            uint32_t af[4], b0, b1, b2, b3;
            ldsm4(af[0], af[1], af[2], af[3], aBase + kk * 32);
            ldsm4t(b0, b1, b2, b3, bBase + kk * 16 * SK_S * 2);
            uint32_t bfA[2] = {b0, b2}, bfB[2] = {b1, b3};
            mma_f16(acc[0], af, bfA);
            mma_f16(acc[1], af, bfB);
        }
        const float tval = temp[h];
        const float rq0 = rs[mb + r] * tval;
        const float rq8 = rs[mb + r + 8] * tval;
#pragma unroll
        for (int t = 0; t < 2; t++) {
            int col = nb + t * 8 + 2 * qq;
            const float rk0 = rs[64 + col], rk1 = rs[64 + col + 1];
            sS[(mb + r) * SS_S + col]         = acc[t][0] * rq0 * rk0;
            sS[(mb + r) * SS_S + col + 1]     = acc[t][1] * rq0 * rk1;
            sS[(mb + r + 8) * SS_S + col]     = acc[t][2] * rq8 * rk0;
            sS[(mb + r + 8) * SS_S + col + 1] = acc[t][3] * rq8 * rk1;
        }
    }
    __syncthreads();

    // ---- parallel softmax: 8 threads per row, registers only ----
    {
        const int row = tid >> 3, sub = tid & 7;
        float v[8];
#pragma unroll
        for (int i = 0; i < 8; i++) v[i] = sS[row * SS_S + sub + 8 * i];
        float mx = v[0];
#pragma unroll
        for (int i = 1; i < 8; i++) mx = fmaxf(mx, v[i]);
#pragma unroll
        for (int o = 1; o < 8; o <<= 1) mx = fmaxf(mx, __shfl_xor_sync(0xffffffffu, mx, o));
        float sum = 0.0f;
#pragma unroll
        for (int i = 0; i < 8; i++) { v[i] = __expf(v[i] - mx); sum += v[i]; }
#pragma unroll
        for (int o = 1; o < 8; o <<= 1) sum += __shfl_xor_sync(0xffffffffu, sum, o);
        const float inv = 1.0f / sum;
        __syncthreads();                       // all reads done before fp16 overwrite
        __half* pp = (__half*)sS;              // hP view, row stride HP_S halves
#pragma unroll
        for (int i = 0; i < 8; i++)
            pp[row * HP_S + sub + 8 * i] = __float2half(v[i] * inv);
    }
    __syncthreads();

    // ---- P4: x[64,256] = P @ v^T -> hM (v B-frags from contiguous global) ----
    {
        const int mb = (wid & 3) * 16;
        const int nb = (wid >> 2) * 64;
        const uint32_t aBase = sbase +
            ((mb + jj + (g & 1) * 8) * HP_S + (g >> 1) * 8) * 2;
        float acc[8][4];
#pragma unroll
        for (int i = 0; i < 8; i++)
#pragma unroll
            for (int k = 0; k < 4; k++) acc[i][k] = 0.0f;
        const int k0l = 2 * qq;
#pragma unroll
        for (int kk = 0; kk < 4; kk++) {
            uint32_t af[4];
            ldsm4(af[0], af[1], af[2], af[3], aBase + kk * 32);
#pragma unroll
            for (int nb8 = 0; nb8 < 8; nb8++) {
                const int row = nb + nb8 * 8 + r;
                uint32_t bf[2] = {0u, 0u};
                if (row < NT) {
                    const __half* bp = vp + row * HD + kk * 16 + k0l;
                    bf[0] = *(const uint32_t*)bp;
                    bf[1] = *(const uint32_t*)(bp + 8);
                }
                mma_f16(acc[nb8], af, bf);
            }
        }
#pragma unroll
        for (int nb8 = 0; nb8 < 8; nb8++) {
            int col = nb + nb8 * 8 + 2 * qq;
            *(__half2*)&hM[(mb + r) * HM_S + col]     = __floats2half2_rn(acc[nb8][0], acc[nb8][1]);
            *(__half2*)&hM[(mb + r + 8) * HM_S + col] = __floats2half2_rn(acc[nb8][2], acc[nb8][3]);
        }
    }
    __syncthreads();

    // ---- P5: out[64,128] = x @ xmH^T -> sOut fp32 [q][d] (overlays sK) ----
    {
        const int mb = (wid & 3) * 16;
        const int nb = (wid >> 2) * 32;
        const uint32_t aBase = sbase +
            (OFF_HM + (mb + jj + (g & 1) * 8) * HM_S + (g >> 1) * 8) * 2;
        float acc[4][4];
#pragma unroll
        for (int i = 0; i < 4; i++)
#pragma unroll
            for (int k = 0; k < 4; k++) acc[i][k] = 0.0f;
        const int k0l = 2 * qq;
#pragma unroll
        for (int kk = 0; kk < 16; kk++) {
            uint32_t af[4];
            ldsm4(af[0], af[1], af[2], af[3], aBase + kk * 32);
#pragma unroll
            for (int nb8 = 0; nb8 < 4; nb8++) {
                const __half* bp = xmH + (nb + nb8 * 8 + r) * 256 + kk * 16 + k0l;
                uint32_t bf[2];
                bf[0] = *(const uint32_t*)bp;
                bf[1] = *(const uint32_t*)(bp + 8);
                mma_f16(acc[nb8], af, bf);
            }
        }
#pragma unroll
        for (int nb8 = 0; nb8 < 4; nb8++) {
            int q0 = nb + nb8 * 8 + 2 * qq;
            int d0 = mb + r;
            sOut[q0 * SO_S + d0]           = acc[nb8][0];
            sOut[(q0 + 1) * SO_S + d0]     = acc[nb8][1];
            sOut[q0 * SO_S + d0 + 8]       = acc[nb8][2];
            sOut[(q0 + 1) * SO_S + d0 + 8] = acc[nb8][3];
        }
    }
    __syncthreads();

    // ---- epilogue: coalesced fp16 store of q<100 rows (row-major y) ----
    for (int i = tid; i < NQ * 32; i += 512) {
        int q = i >> 5, c = i & 31;
        float a0 = sOut[q * SO_S + 2 * c];
        float a1 = sOut[q * SO_S + 2 * c + 1];
        *(__half2*)&y[((size_t)q * BSZ + b) * E + h * HD + 2 * c] =
            __floats2half2_rn(a0, a1);
    }
}

// ---------------------------------------------------------------------------
// Launch: f2h_all(1), norm_map(2), gemm_q(3), gemm_k(4=profiled), gemm_v(5),
//         attn(6), gemm_out(7)
// ---------------------------------------------------------------------------
extern "C" void kernel_launch(void* const* d_in, const int* in_sizes, int n_in,
                              void* d_out, int out_size)
{
    const float* query = (const float*)d_in[0];
    const float* key   = (const float*)d_in[1];
    const float* value = (const float*)d_in[2];
    const float* ipw   = (const float*)d_in[3];
    const float* ipb   = (const float*)d_in[4];
    const float* opw   = (const float*)d_in[5];
    const float* opb   = (const float*)d_in[6];
    const float* temp  = (const float*)d_in[7];
    const float* qmap  = (const float*)d_in[8];
    const float* xmap  = (const float*)d_in[9];
    float* out = (float*)d_out;

    __half *qh, *kh, *vh, *wh, *owh, *yh, *qmH, *xmH, *qph, *kph, *vph;
    cudaGetSymbolAddress((void**)&qh,  g_qh);
    cudaGetSymbolAddress((void**)&kh,  g_kh);
    cudaGetSymbolAddress((void**)&vh,  g_vh);
    cudaGetSymbolAddress((void**)&wh,  g_wh);
    cudaGetSymbolAddress((void**)&owh, g_owh);
    cudaGetSymbolAddress((void**)&yh,  g_yh);
    cudaGetSymbolAddress((void**)&qmH, g_qmH);
    cudaGetSymbolAddress((void**)&xmH, g_xmH);
    cudaGetSymbolAddress((void**)&qph, g_qph);
    cudaGetSymbolAddress((void**)&kph, g_kph);
    cudaGetSymbolAddress((void**)&vph, g_vph);

    cudaFuncSetAttribute(gemm_h<true>,  cudaFuncAttributeMaxDynamicSharedMemorySize, GEMM_SMEM);
    cudaFuncSetAttribute(gemm_h<false>, cudaFuncAttributeMaxDynamicSharedMemorySize, GEMM_SMEM);
    cudaFuncSetAttribute(attn_tc, cudaFuncAttributeMaxDynamicSharedMemorySize,
                         ATTN_SMEM_BYTES);

    dim3 gq(6, (NQ * BSZ) / 128);
    dim3 gk(6, (NT * BSZ) / 128);

    f2h_all<<<(TOT4 + 255) / 256, 256>>>(
        (const float4*)query, (const float4*)key, (const float4*)value,
        (const float4*)ipw, (const float4*)opw,
        (__half2*)qh, (__half2*)kh, (__half2*)vh, (__half2*)wh, (__half2*)owh);
    norm_map_h<<<48, 256>>>(qmap, xmap, qmH, xmH);
    gemm_h<true><<<gq, 256, GEMM_SMEM>>>(qh, wh,             ipb,         qph, NQ);
    gemm_h<true><<<gk, 256, GEMM_SMEM>>>(kh, wh + E * E,     ipb + E,     kph, NT);
    gemm_h<true><<<gk, 256, GEMM_SMEM>>>(vh, wh + 2 * E * E, ipb + 2 * E, vph, NT);
    attn_tc<<<BH, 512, ATTN_SMEM_BYTES>>>(qph, kph, vph, qmH, xmH, temp, yh);
    gemm_h<false><<<gq, 256, GEMM_SMEM>>>(yh, owh, opb, out, 0);
}

// round 17
// speedup vs baseline: 1.0007x; 1.0007x over previous
#include <cuda_runtime.h>
#include <cuda_fp16.h>
#include <math.h>
#include <cstdint>

// Problem constants
#define NQ   100
#define NT   197
#define BSZ  128
#define E    768
#define NH   12
#define HD   64
#define BH   (BSZ*NH)

// ---------------------------------------------------------------------------
// Device scratch
// ---------------------------------------------------------------------------
__device__ __half g_qh[NQ * BSZ * E];      // fp16 inputs to projections
__device__ __half g_kh[NT * BSZ * E];
__device__ __half g_vh[NT * BSZ * E];
__device__ __half g_wh[3 * E * E];
__device__ __half g_owh[E * E];
__device__ __half g_qph[BH * NQ * HD];     // fp16 projections, [bh][tok][d]
__device__ __half g_kph[BH * NT * HD];
__device__ __half g_vph[BH * NT * HD];
__device__ __half g_yh[NQ * BSZ * E];      // fp16 attention output (row-major)
__device__ __half g_qmH[256 * 112];        // normalized q_mapper fp16 [t][q], zero-pad
__device__ __half g_xmH[128 * 256];        // normalized x_mapper fp16 [q][t], zero-pad

// ---------------------------------------------------------------------------
// Common PTX helpers
// ---------------------------------------------------------------------------
__device__ __forceinline__ uint32_t smem_u32(const void* p) {
    uint32_t a;
    asm("{ .reg .u64 t; cvta.to.shared.u64 t, %1; cvt.u32.u64 %0, t; }"
        : "=r"(a) : "l"(p));
    return a;
}
__device__ __forceinline__ void cpa16(uint32_t dst, const void* src) {
    asm volatile("cp.async.cg.shared.global [%0], [%1], 16;" :: "r"(dst), "l"(src));
}
__device__ __forceinline__ void ldsm4(uint32_t& r0, uint32_t& r1, uint32_t& r2,
                                      uint32_t& r3, uint32_t addr) {
    asm volatile("ldmatrix.sync.aligned.m8n8.x4.shared.b16 {%0,%1,%2,%3}, [%4];"
                 : "=r"(r0), "=r"(r1), "=r"(r2), "=r"(r3) : "r"(addr));
}
__device__ __forceinline__ void ldsm4t(uint32_t& r0, uint32_t& r1, uint32_t& r2,
                                       uint32_t& r3, uint32_t addr) {
    asm volatile("ldmatrix.sync.aligned.m8n8.x4.trans.shared.b16 {%0,%1,%2,%3}, [%4];"
                 : "=r"(r0), "=r"(r1), "=r"(r2), "=r"(r3) : "r"(addr));
}
__device__ __forceinline__ void mma_f16(float* c, const uint32_t* a, const uint32_t* b) {
    asm volatile(
        "mma.sync.aligned.m16n8k16.row.col.f32.f16.f16.f32 "
        "{%0,%1,%2,%3}, {%4,%5,%6,%7}, {%8,%9}, {%0,%1,%2,%3};"
        : "+f"(c[0]), "+f"(c[1]), "+f"(c[2]), "+f"(c[3])
        : "r"(a[0]), "r"(a[1]), "r"(a[2]), "r"(a[3]), "r"(b[0]), "r"(b[1]));
}

// ---------------------------------------------------------------------------
// One fused fp32 -> fp16 conversion for all five tensors
// ---------------------------------------------------------------------------
#define NQ4 (NQ * BSZ * E / 4)
#define NT4 (NT * BSZ * E / 4)
#define W4  (3 * E * E / 4)
#define OW4 (E * E / 4)
#define TOT4 (NQ4 + 2 * NT4 + W4 + OW4)

__global__ void f2h_all(const float4* __restrict__ q, const float4* __restrict__ k,
                        const float4* __restrict__ v, const float4* __restrict__ w,
                        const float4* __restrict__ ow,
                        __half2* qh, __half2* kh, __half2* vh, __half2* wh, __half2* owh)
{
    int i = blockIdx.x * blockDim.x + threadIdx.x;
    if (i >= TOT4) return;
    const float4* src; __half2* dst; int j;
    if (i < NQ4)                        { src = q;  dst = qh;  j = i; }
    else if (i < NQ4 + NT4)             { src = k;  dst = kh;  j = i - NQ4; }
    else if (i < NQ4 + 2 * NT4)         { src = v;  dst = vh;  j = i - NQ4 - NT4; }
    else if (i < NQ4 + 2 * NT4 + W4)    { src = w;  dst = wh;  j = i - NQ4 - 2 * NT4; }
    else                                { src = ow; dst = owh; j = i - NQ4 - 2 * NT4 - W4; }
    float4 val = src[j];
    dst[2 * j]     = __floats2half2_rn(val.x, val.y);
    dst[2 * j + 1] = __floats2half2_rn(val.z, val.w);
}

// ---------------------------------------------------------------------------
// fp16 mma.sync GEMM (unchanged mainloop; scatter epilogue for OUTH=true)
// ---------------------------------------------------------------------------
#define PADH      40
#define MAT_H     (128 * PADH)
#define STG_B     (2 * MAT_H * 2)
#define GEMM_SMEM (4 * STG_B)

template<bool OUTH>
__global__ __launch_bounds__(256, 2)
void gemm_h(const __half* __restrict__ A, const __half* __restrict__ W,
            const float* __restrict__ bias, void* __restrict__ Cv, int NTOK)
{
    extern __shared__ __half smh[];
    const uint32_t sb = smem_u32(smh);
    const int tid  = threadIdx.x;
    const int lane = tid & 31;
    const int wid  = tid >> 5;
    const int m0 = blockIdx.y * 128, n0 = blockIdx.x * 128;
    const int wm = (wid >> 2) * 64;
    const int wn = (wid & 3) * 32;

    const int prow = tid >> 1;
    const int pseg = (tid & 1) * 16;
    const __half* gA = A + (size_t)(m0 + prow) * E + pseg;
    const __half* gB = W + (size_t)(n0 + prow) * E + pseg;
    const uint32_t sAa = sb + (prow * PADH + pseg) * 2;
    const uint32_t sBa = sAa + MAT_H * 2;

#define LOAD_STAGE(st, kc) do { \
    const uint32_t so = (uint32_t)(st) * STG_B; \
    const __half* ga = gA + (kc) * 32; \
    const __half* gb = gB + (kc) * 32; \
    cpa16(sAa + so,      ga);     cpa16(sAa + so + 16, ga + 8); \
    cpa16(sBa + so,      gb);     cpa16(sBa + so + 16, gb + 8); \
    asm volatile("cp.async.commit_group;"); \
} while (0)

    LOAD_STAGE(0, 0);
    LOAD_STAGE(1, 1);
    LOAD_STAGE(2, 2);

    float acc[4][4][4];
#pragma unroll
    for (int i = 0; i < 4; i++)
#pragma unroll
        for (int j = 0; j < 4; j++)
#pragma unroll
            for (int k = 0; k < 4; k++) acc[i][j][k] = 0.0f;

    const int g = lane >> 3, j = lane & 7;
    const uint32_t aoff = ((wm + j + (g & 1) * 8) * PADH + (g >> 1) * 8) * 2;
    const uint32_t boff = ((wn + j + (g & 1) * 8) * PADH + (g >> 1) * 8) * 2 + MAT_H * 2;

    for (int kc = 0; kc < 24; kc++) {
        asm volatile("cp.async.wait_group 2;");
        __syncthreads();
        const uint32_t base = sb + (uint32_t)(kc & 3) * STG_B;

#pragma unroll
        for (int s = 0; s < 2; s++) {
            const uint32_t k0b = s * 32;
            uint32_t bf[4][2];
            ldsm4(bf[0][0], bf[1][0], bf[0][1], bf[1][1], base + boff + k0b);
            ldsm4(bf[2][0], bf[3][0], bf[2][1], bf[3][1],
                  base + boff + 16 * PADH * 2 + k0b);
#pragma unroll
            for (int mt = 0; mt < 4; mt++) {
                uint32_t af[4];
                ldsm4(af[0], af[1], af[2], af[3],
                      base + aoff + mt * 16 * PADH * 2 + k0b);
#pragma unroll
                for (int nt = 0; nt < 4; nt++)
                    mma_f16(acc[mt][nt], af, bf[nt]);
            }
        }
        if (kc + 3 < 24) {
            LOAD_STAGE((kc + 3) & 3, kc + 3);
        } else {
            asm volatile("cp.async.commit_group;");
        }
    }

    const int r = lane >> 2, q = lane & 3;
#pragma unroll
    for (int mt = 0; mt < 4; mt++) {
        const int row = m0 + wm + mt * 16 + r;
#pragma unroll
        for (int nt = 0; nt < 4; nt++) {
            const int col = n0 + wn + nt * 8 + 2 * q;
            const float b0 = bias[col], b1 = bias[col + 1];
            if (OUTH) {
                __half* C = (__half*)Cv;
                const int tok = blockIdx.y;
                const int bb  = row & 127;
                const int h   = col >> 6, d = col & 63;
                const size_t base0 = ((size_t)(bb * NH + h) * NTOK + tok) * HD + d;
                const size_t base1 = ((size_t)(((row + 8) & 127) * NH + h) * NTOK + tok) * HD + d;
                *(__half2*)&C[base0] =
                    __floats2half2_rn(acc[mt][nt][0] + b0, acc[mt][nt][1] + b1);
                *(__half2*)&C[base1] =
                    __floats2half2_rn(acc[mt][nt][2] + b0, acc[mt][nt][3] + b1);
            } else {
                float* C = (float*)Cv;
                *(float2*)&C[(size_t)row * E + col] =
                    make_float2(acc[mt][nt][0] + b0, acc[mt][nt][1] + b1);
                *(float2*)&C[(size_t)(row + 8) * E + col] =
                    make_float2(acc[mt][nt][2] + b0, acc[mt][nt][3] + b1);
            }
        }
    }
#undef LOAD_STAGE
}

// ---------------------------------------------------------------------------
// Normalize mapper matrices -> zero-padded fp16
// ---------------------------------------------------------------------------
__global__ void norm_map_h(const float* __restrict__ qm, const float* __restrict__ xm,
                           __half* __restrict__ qmH, __half* __restrict__ xmH)
{
    int row  = blockIdx.x * (blockDim.x >> 5) + (threadIdx.x >> 5);
    int lane = threadIdx.x & 31;
    const __half hz = __float2half(0.0f);
    if (row < 256) {
        __half* dst = qmH + row * 112;
        if (row < NT) {
            const float* x = qm + row * NQ;
            float ss = 0.0f;
            for (int i = lane; i < NQ; i += 32) { float v = x[i]; ss += v * v; }
#pragma unroll
            for (int o = 16; o; o >>= 1) ss += __shfl_xor_sync(0xffffffffu, ss, o);
            float s = 1.0f / fmaxf(sqrtf(ss), 1e-12f);
            for (int i = lane; i < 112; i += 32)
                dst[i] = (i < NQ) ? __float2half(x[i] * s) : hz;
        } else {
            for (int i = lane; i < 112; i += 32) dst[i] = hz;
        }
    } else if (row < 384) {
        int r = row - 256;
        __half* dst = xmH + r * 256;
        if (r < NQ) {
            const float* x = xm + r * NT;
            float ss = 0.0f;
            for (int i = lane; i < NT; i += 32) { float v = x[i]; ss += v * v; }
#pragma unroll
            for (int o = 16; o; o >>= 1) ss += __shfl_xor_sync(0xffffffffu, ss, o);
            float s = 1.0f / fmaxf(sqrtf(ss), 1e-12f);
            for (int i = lane; i < 256; i += 32)
                dst[i] = (i < NT) ? __float2half(x[i] * s) : hz;
        } else {
            for (int i = lane; i < 256; i += 32) dst[i] = hz;
        }
    }
}

// ---------------------------------------------------------------------------
// Tensor-core fused attention v2.
//  - q/k loaded NATURAL [tok][64] via cp.async (coalesced, no transpose stores)
//  - trans-ldmatrix supplies qn/kn fragments
//  - L2-norm scales rs[128] folded into P2 epilogue (linearity)
//  - parallel register-only softmax (8 threads/row)
// SMEM (halves): sQ[112][72] (later sS/hP) | sK[256][72] (later sOut) |
//                hM[64][264] | rs[128]f
// ---------------------------------------------------------------------------
#define SQ_S 72
#define SK_S 72
#define HM_S 264
#define SS_S 68
#define HP_S 136
#define SO_S 66
#define OFF_SK 8704
#define OFF_HM (OFF_SK + 18432)           // 27136
#define OFF_RS (OFF_HM + 16896)           // 44032 halves
#define ATTN_SMEM_BYTES ((OFF_RS + 256) * 2)   // 88576

__global__ __launch_bounds__(512, 2)
void attn_tc(const __half* __restrict__ q_t, const __half* __restrict__ k_t,
             const __half* __restrict__ v_t, const __half* __restrict__ qmH,
             const __half* __restrict__ xmH, const float* __restrict__ temp,
             __half* __restrict__ y)
{
    extern __shared__ __half sh[];
    __half* sQ = sh;                       // [112][72] natural [tok][d]
    __half* sK = sh + OFF_SK;              // [256][72] natural [tok][e]
    __half* hM = sh + OFF_HM;              // [64][264] k-major qm / x
    float*  sS   = (float*)sh;             // [64][68]  overlays sQ after P1
    float*  sOut = (float*)(sh + OFF_SK);  // [128][66] overlays sK after P2
    float*  rs   = (float*)(sh + OFF_RS);  // [128] 1/norm scales (q:0-63, k:64-127)
    const uint32_t sbase = smem_u32(sh);

    const int bh = blockIdx.x;
    const int b  = bh / NH;
    const int h  = bh % NH;
    const __half* qp = q_t + (size_t)bh * (NQ * HD);
    const __half* kp = k_t + (size_t)bh * (NT * HD);
    const __half* vp = v_t + (size_t)bh * (NT * HD);

    const int tid  = threadIdx.x;
    const int wid  = tid >> 5;
    const int lane = tid & 31;
    const int g    = lane >> 3;
    const int jj   = lane & 7;
    const int r    = lane >> 2;
    const int qq   = lane & 3;

    // ---- zero pad tails: sQ rows 100..111, sK rows 197..255 ----
    {
        uint32_t* zq = (uint32_t*)(sQ + 100 * SQ_S);   // 432 words
        uint32_t* zk = (uint32_t*)(sK + 197 * SK_S);   // 2124 words
        for (int i = tid; i < 432 + 2124; i += 512) {
            if (i < 432) zq[i] = 0u; else zk[i - 432] = 0u;
        }
    }

    // ---- cp.async natural q/k rows (16B segments) ----
    for (int i = tid; i < (NQ + NT) * 8; i += 512) {
        if (i < NQ * 8) {
            int rr = i >> 3, s = i & 7;
            cpa16(sbase + (rr * SQ_S + s * 8) * 2, qp + rr * HD + s * 8);
        } else {
            int k = i - NQ * 8;
            int rr = k >> 3, s = k & 7;
            cpa16(sbase + OFF_SK * 2 + (rr * SK_S + s * 8) * 2, kp + rr * HD + s * 8);
        }
    }
    asm volatile("cp.async.commit_group;");
    asm volatile("cp.async.wait_group 0;");
    __syncthreads();

    // ---- column L2 norms -> rs[128] (warp w handles 8 channels) ----
    {
#pragma unroll
        for (int cc = 0; cc < 8; cc++) {
            int ch = wid * 8 + cc;
            float ss = 0.0f;
            if (ch < 64) {
                for (int i = lane; i < 112; i += 32) {
                    float v = __half2float(sQ[i * SQ_S + ch]); ss += v * v;
                }
            } else {
                int e = ch - 64;
                for (int i = lane; i < 256; i += 32) {
                    float v = __half2float(sK[i * SK_S + e]); ss += v * v;
                }
            }
#pragma unroll
            for (int o = 16; o; o >>= 1) ss += __shfl_xor_sync(0xffffffffu, ss, o);
            if (lane == 0) rs[ch] = 1.0f / fmaxf(sqrtf(ss), 1e-12f);
        }
    }
    __syncthreads();

    // ---- P1: qm[64,256] = q @ qmH^T -> hM (A via trans-ldsm from natural sQ) ----
    {
        const int mb = (wid & 3) * 16;
        const int nb = (wid >> 2) * 64;
        const uint32_t aBase = sbase +
            ((jj + (g >> 1) * 8) * SQ_S + mb + (g & 1) * 8) * 2;
        float acc[8][4];
#pragma unroll
        for (int i = 0; i < 8; i++)
#pragma unroll
            for (int k = 0; k < 4; k++) acc[i][k] = 0.0f;
        const int k0l = 2 * qq;
#pragma unroll
        for (int kk = 0; kk < 7; kk++) {
            uint32_t af[4];
            ldsm4t(af[0], af[1], af[2], af[3], aBase + kk * 16 * SQ_S * 2);
#pragma unroll
            for (int nb8 = 0; nb8 < 8; nb8++) {
                const __half* bp = qmH + (nb + nb8 * 8 + r) * 112 + kk * 16 + k0l;
                uint32_t bf[2];
                bf[0] = *(const uint32_t*)bp;
                bf[1] = *(const uint32_t*)(bp + 8);
                mma_f16(acc[nb8], af, bf);
            }
        }
#pragma unroll
        for (int nb8 = 0; nb8 < 8; nb8++) {
            int col = nb + nb8 * 8 + 2 * qq;
            *(__half2*)&hM[(mb + r) * HM_S + col]     = __floats2half2_rn(acc[nb8][0], acc[nb8][1]);
            *(__half2*)&hM[(mb + r + 8) * HM_S + col] = __floats2half2_rn(acc[nb8][2], acc[nb8][3]);
        }
    }
    __syncthreads();

    // ---- P2: S[64,64] = qm @ k^T -> sS fp32, scaled by temp*rs_q*rs_k ----
    {
        const int mb = (wid & 3) * 16;
        const int nb = (wid >> 2) * 16;
        const uint32_t aBase = sbase +
            (OFF_HM + (mb + jj + (g & 1) * 8) * HM_S + (g >> 1) * 8) * 2;
        const uint32_t bBase = sbase +
            (OFF_SK + (jj + (g >> 1) * 8) * SK_S + nb + (g & 1) * 8) * 2;
        float acc[2][4];
#pragma unroll
        for (int i = 0; i < 2; i++)
#pragma unroll
            for (int k = 0; k < 4; k++) acc[i][k] = 0.0f;
#pragma unroll
        for (int kk = 0; kk < 16; kk++) {
            uint32_t af[4], b0, b1, b2, b3;
            ldsm4(af[0], af[1], af[2], af[3], aBase + kk * 32);
            ldsm4t(b0, b1, b2, b3, bBase + kk * 16 * SK_S * 2);
            uint32_t bfA[2] = {b0, b2}, bfB[2] = {b1, b3};
            mma_f16(acc[0], af, bfA);
            mma_f16(acc[1], af, bfB);
        }
        const float tval = temp[h];
        const float rq0 = rs[mb + r] * tval;
        const float rq8 = rs[mb + r + 8] * tval;
#pragma unroll
        for (int t = 0; t < 2; t++) {
            int col = nb + t * 8 + 2 * qq;
            const float rk0 = rs[64 + col], rk1 = rs[64 + col + 1];
            sS[(mb + r) * SS_S + col]         = acc[t][0] * rq0 * rk0;
            sS[(mb + r) * SS_S + col + 1]     = acc[t][1] * rq0 * rk1;
            sS[(mb + r + 8) * SS_S + col]     = acc[t][2] * rq8 * rk0;
            sS[(mb + r + 8) * SS_S + col + 1] = acc[t][3] * rq8 * rk1;
        }
    }
    __syncthreads();

    // ---- parallel softmax: 8 threads per row, registers only ----
    {
        const int row = tid >> 3, sub = tid & 7;
        float v[8];
#pragma unroll
        for (int i = 0; i < 8; i++) v[i] = sS[row * SS_S + sub + 8 * i];
        float mx = v[0];
#pragma unroll
        for (int i = 1; i < 8; i++) mx = fmaxf(mx, v[i]);
#pragma unroll
        for (int o = 1; o < 8; o <<= 1) mx = fmaxf(mx, __shfl_xor_sync(0xffffffffu, mx, o));
        float sum = 0.0f;
#pragma unroll
        for (int i = 0; i < 8; i++) { v[i] = __expf(v[i] - mx); sum += v[i]; }
#pragma unroll
        for (int o = 1; o < 8; o <<= 1) sum += __shfl_xor_sync(0xffffffffu, sum, o);
        const float inv = 1.0f / sum;
        __syncthreads();                       // all reads done before fp16 overwrite
        __half* pp = (__half*)sS;              // hP view, row stride HP_S halves
#pragma unroll
        for (int i = 0; i < 8; i++)
            pp[row * HP_S + sub + 8 * i] = __float2half(v[i] * inv);
    }
    __syncthreads();

    // ---- P4: x[64,256] = P @ v^T -> hM (v B-frags from contiguous global) ----
    {
        const int mb = (wid & 3) * 16;
        const int nb = (wid >> 2) * 64;
        const uint32_t aBase = sbase +
            ((mb + jj + (g & 1) * 8) * HP_S + (g >> 1) * 8) * 2;
        float acc[8][4];
#pragma unroll
        for (int i = 0; i < 8; i++)
#pragma unroll
            for (int k = 0; k < 4; k++) acc[i][k] = 0.0f;
        const int k0l = 2 * qq;
#pragma unroll
        for (int kk = 0; kk < 4; kk++) {
            uint32_t af[4];
            ldsm4(af[0], af[1], af[2], af[3], aBase + kk * 32);
#pragma unroll
            for (int nb8 = 0; nb8 < 8; nb8++) {
                const int row = nb + nb8 * 8 + r;
                uint32_t bf[2] = {0u, 0u};
                if (row < NT) {
                    const __half* bp = vp + row * HD + kk * 16 + k0l;
                    bf[0] = *(const uint32_t*)bp;
                    bf[1] = *(const uint32_t*)(bp + 8);
                }
                mma_f16(acc[nb8], af, bf);
            }
        }
#pragma unroll
        for (int nb8 = 0; nb8 < 8; nb8++) {
            int col = nb + nb8 * 8 + 2 * qq;
            *(__half2*)&hM[(mb + r) * HM_S + col]     = __floats2half2_rn(acc[nb8][0], acc[nb8][1]);
            *(__half2*)&hM[(mb + r + 8) * HM_S + col] = __floats2half2_rn(acc[nb8][2], acc[nb8][3]);
        }
    }
    __syncthreads();

    // ---- P5: out[64,128] = x @ xmH^T -> sOut fp32 [q][d] (overlays sK) ----
    {
        const int mb = (wid & 3) * 16;
        const int nb = (wid >> 2) * 32;
        const uint32_t aBase = sbase +
            (OFF_HM + (mb + jj + (g & 1) * 8) * HM_S + (g >> 1) * 8) * 2;
        float acc[4][4];
#pragma unroll
        for (int i = 0; i < 4; i++)
#pragma unroll
            for (int k = 0; k < 4; k++) acc[i][k] = 0.0f;
        const int k0l = 2 * qq;
#pragma unroll
        for (int kk = 0; kk < 16; kk++) {
            uint32_t af[4];
            ldsm4(af[0], af[1], af[2], af[3], aBase + kk * 32);
#pragma unroll
            for (int nb8 = 0; nb8 < 4; nb8++) {
                const __half* bp = xmH + (nb + nb8 * 8 + r) * 256 + kk * 16 + k0l;
                uint32_t bf[2];
                bf[0] = *(const uint32_t*)bp;
                bf[1] = *(const uint32_t*)(bp + 8);
                mma_f16(acc[nb8], af, bf);
            }
        }
#pragma unroll
        for (int nb8 = 0; nb8 < 4; nb8++) {
            int q0 = nb + nb8 * 8 + 2 * qq;
            int d0 = mb + r;
            sOut[q0 * SO_S + d0]           = acc[nb8][0];
            sOut[(q0 + 1) * SO_S + d0]     = acc[nb8][1];
            sOut[q0 * SO_S + d0 + 8]       = acc[nb8][2];
            sOut[(q0 + 1) * SO_S + d0 + 8] = acc[nb8][3];
        }
    }
    __syncthreads();

    // ---- epilogue: coalesced fp16 store of q<100 rows (row-major y) ----
    for (int i = tid; i < NQ * 32; i += 512) {
        int q = i >> 5, c = i & 31;
        float a0 = sOut[q * SO_S + 2 * c];
        float a1 = sOut[q * SO_S + 2 * c + 1];
        *(__half2*)&y[((size_t)q * BSZ + b) * E + h * HD + 2 * c] =
            __floats2half2_rn(a0, a1);
    }
}

// ---------------------------------------------------------------------------
// Launch: f2h_all(1), norm_map(2), gemm_q(3), gemm_k(4=profiled), gemm_v(5),
//         attn(6), gemm_out(7)
// ---------------------------------------------------------------------------
extern "C" void kernel_launch(void* const* d_in, const int* in_sizes, int n_in,
                              void* d_out, int out_size)
{
    const float* query = (const float*)d_in[0];
    const float* key   = (const float*)d_in[1];
    const float* value = (const float*)d_in[2];
    const float* ipw   = (const float*)d_in[3];
    const float* ipb   = (const float*)d_in[4];
    const float* opw   = (const float*)d_in[5];
    const float* opb   = (const float*)d_in[6];
    const float* temp  = (const float*)d_in[7];
    const float* qmap  = (const float*)d_in[8];
    const float* xmap  = (const float*)d_in[9];
    float* out = (float*)d_out;

    __half *qh, *kh, *vh, *wh, *owh, *yh, *qmH, *xmH, *qph, *kph, *vph;
    cudaGetSymbolAddress((void**)&qh,  g_qh);
    cudaGetSymbolAddress((void**)&kh,  g_kh);
    cudaGetSymbolAddress((void**)&vh,  g_vh);
    cudaGetSymbolAddress((void**)&wh,  g_wh);
    cudaGetSymbolAddress((void**)&owh, g_owh);
    cudaGetSymbolAddress((void**)&yh,  g_yh);
    cudaGetSymbolAddress((void**)&qmH, g_qmH);
    cudaGetSymbolAddress((void**)&xmH, g_xmH);
    cudaGetSymbolAddress((void**)&qph, g_qph);
    cudaGetSymbolAddress((void**)&kph, g_kph);
    cudaGetSymbolAddress((void**)&vph, g_vph);

    cudaFuncSetAttribute(gemm_h<true>,  cudaFuncAttributeMaxDynamicSharedMemorySize, GEMM_SMEM);
    cudaFuncSetAttribute(gemm_h<false>, cudaFuncAttributeMaxDynamicSharedMemorySize, GEMM_SMEM);
    cudaFuncSetAttribute(attn_tc, cudaFuncAttributeMaxDynamicSharedMemorySize,
                         ATTN_SMEM_BYTES);

    dim3 gq(6, (NQ * BSZ) / 128);
    dim3 gk(6, (NT * BSZ) / 128);

    f2h_all<<<(TOT4 + 255) / 256, 256>>>(
        (const float4*)query, (const float4*)key, (const float4*)value,
        (const float4*)ipw, (const float4*)opw,
        (__half2*)qh, (__half2*)kh, (__half2*)vh, (__half2*)wh, (__half2*)owh);
    norm_map_h<<<48, 256>>>(qmap, xmap, qmH, xmH);
    gemm_h<true><<<gq, 256, GEMM_SMEM>>>(qh, wh,             ipb,         qph, NQ);
    gemm_h<true><<<gk, 256, GEMM_SMEM>>>(kh, wh + E * E,     ipb + E,     kph, NT);
    gemm_h<true><<<gk, 256, GEMM_SMEM>>>(vh, wh + 2 * E * E, ipb + 2 * E, vph, NT);
    attn_tc<<<BH, 512, ATTN_SMEM_BYTES>>>(qph, kph, vph, qmH, xmH, temp, yh);
    gemm_h<false><<<gq, 256, GEMM_SMEM>>>(yh, owh, opb, out, 0);
}